// round 1
// baseline (speedup 1.0000x reference)
#include <cuda_runtime.h>

#define NPTS 16384
#define NS   8192
#define KNB  10
#define R2   0.0625f
#define FPS_T 512
#define FPS_P 16   // pairs per thread -> 32 points per thread

// ---------------- global scratch (no allocation allowed) ----------------
__device__ __align__(16) float g_px[NPTS];
__device__ __align__(16) float g_py[NPTS];
__device__ __align__(16) float g_pz[NPTS];
__device__ float g_cx[NS], g_cy[NS], g_cz[NS];
__device__ int   g_src[NS * KNB];

// ---------------- packed f32x2 helpers (bit-exact IEEE RN) ----------------
__device__ __forceinline__ unsigned long long f2_add(unsigned long long a, unsigned long long b) {
    unsigned long long r; asm("add.rn.f32x2 %0, %1, %2;" : "=l"(r) : "l"(a), "l"(b)); return r;
}
__device__ __forceinline__ unsigned long long f2_mul(unsigned long long a, unsigned long long b) {
    unsigned long long r; asm("mul.rn.f32x2 %0, %1, %2;" : "=l"(r) : "l"(a), "l"(b)); return r;
}
__device__ __forceinline__ unsigned long long pack2(unsigned lo, unsigned hi) {
    unsigned long long r; asm("mov.b64 %0, {%1, %2};" : "=l"(r) : "r"(lo), "r"(hi)); return r;
}
__device__ __forceinline__ void unpack2(unsigned &lo, unsigned &hi, unsigned long long v) {
    asm("mov.b64 {%0, %1}, %2;" : "=r"(lo), "=r"(hi) : "l"(v));
}

// ---------------- K0: AoS -> SoA transpose ----------------
__global__ void prep_kernel(const float* __restrict__ pos) {
    int i = blockIdx.x * blockDim.x + threadIdx.x;
    if (i < NPTS) {
        g_px[i] = pos[3 * i + 0];
        g_py[i] = pos[3 * i + 1];
        g_pz[i] = pos[3 * i + 2];
    }
}

// ---------------- K1: farthest point sampling, single block ----------------
// Exact semantics of the jax scan:
//   last = 0; for s in 0..NS-2: min_d = min(min_d, ||p - p_last||^2);
//   next = argmax(min_d) (first index on ties); centers[s+1] = next.
// Distances computed as ((dx*dx + dy*dy) + dz*dz) with separate RN mul/add
// (no FMA) to match XLA bit-for-bit; f32x2 packs 2 points per instruction.
__global__ __launch_bounds__(FPS_T, 1) void fps_kernel() {
    extern __shared__ unsigned char smem_raw[];
    float2*   s_md   = (float2*)smem_raw;                       // 8192 float2 = 64KB
    unsigned* s_wm   = (unsigned*)(smem_raw + (NPTS / 2) * 8);  // 16 warp maxima
    unsigned* s_bmax = s_wm + 16;
    int*      s_win  = (int*)(s_wm + 17);
    float*    s_last = (float*)(s_wm + 18);

    const int tid  = threadIdx.x;
    const int lane = tid & 31;
    const int wid  = tid >> 5;

    // thread owns point pairs p2 = tid + 512*j  -> global points 2*p2, 2*p2+1
    unsigned long long X[FPS_P], Y[FPS_P], Z[FPS_P];
    const unsigned long long* px2 = (const unsigned long long*)g_px;
    const unsigned long long* py2 = (const unsigned long long*)g_py;
    const unsigned long long* pz2 = (const unsigned long long*)g_pz;
#pragma unroll
    for (int j = 0; j < FPS_P; j++) {
        int p2 = tid + FPS_T * j;
        X[j] = px2[p2]; Y[j] = py2[p2]; Z[j] = pz2[p2];
        s_md[p2] = make_float2(3.402823466e38f, 3.402823466e38f);  // finfo(f32).max
    }
    if (tid == 0) {
        float lx = g_px[0], ly = g_py[0], lz = g_pz[0];
        s_last[0] = lx; s_last[1] = ly; s_last[2] = lz;
        *s_win = 0x7fffffff;
        g_cx[0] = lx; g_cy[0] = ly; g_cz[0] = lz;
    }
    __syncthreads();

    for (int s = 0; s < NS - 1; s++) {
        float lx = s_last[0], ly = s_last[1], lz = s_last[2];
        unsigned nbx = __float_as_uint(-lx);
        unsigned nby = __float_as_uint(-ly);
        unsigned nbz = __float_as_uint(-lz);
        unsigned long long nlx = pack2(nbx, nbx);
        unsigned long long nly = pack2(nby, nby);
        unsigned long long nlz = pack2(nbz, nbz);

        float bv = 0.0f;  // all min_d >= 0
#pragma unroll
        for (int j = 0; j < FPS_P; j++) {
            unsigned long long dx = f2_add(X[j], nlx);   // x - lx (exact)
            unsigned long long dy = f2_add(Y[j], nly);
            unsigned long long dz = f2_add(Z[j], nlz);
            unsigned long long d2 = f2_add(f2_add(f2_mul(dx, dx), f2_mul(dy, dy)), f2_mul(dz, dz));
            unsigned d0u, d1u; unpack2(d0u, d1u, d2);
            float2 m = s_md[tid + FPS_T * j];
            float n0 = fminf(m.x, __uint_as_float(d0u));
            float n1 = fminf(m.y, __uint_as_float(d1u));
            if (n0 < m.x || n1 < m.y) s_md[tid + FPS_T * j] = make_float2(n0, n1);
            bv = fmaxf(bv, fmaxf(n0, n1));
        }

        // two-stage argmax (value via REDUX, index via atomicMin for ties)
        unsigned vb = __float_as_uint(bv);  // positive floats: bit order == value order
        unsigned wm = __reduce_max_sync(0xffffffffu, vb);
        if (lane == 0) s_wm[wid] = wm;
        __syncthreads();
        if (wid == 0) {
            unsigned v = (lane < (FPS_T / 32)) ? s_wm[lane] : 0u;
            unsigned bmx = __reduce_max_sync(0xffffffffu, v);
            if (lane == 0) *s_bmax = bmx;
        }
        __syncthreads();
        unsigned bm = *s_bmax;

        int myg = -1;
        float wx = 0.f, wy = 0.f, wz = 0.f;
        if (vb == bm) {
            bool found = false;
#pragma unroll
            for (int j = 0; j < FPS_P; j++) {
                if (!found) {
                    float2 m = s_md[tid + FPS_T * j];
                    if (__float_as_uint(m.x) == bm) {
                        unsigned alo, ahi, blo, bhi, clo, chi;
                        unpack2(alo, ahi, X[j]); unpack2(blo, bhi, Y[j]); unpack2(clo, chi, Z[j]);
                        myg = 2 * (tid + FPS_T * j);
                        wx = __uint_as_float(alo); wy = __uint_as_float(blo); wz = __uint_as_float(clo);
                        found = true;
                    } else if (__float_as_uint(m.y) == bm) {
                        unsigned alo, ahi, blo, bhi, clo, chi;
                        unpack2(alo, ahi, X[j]); unpack2(blo, bhi, Y[j]); unpack2(clo, chi, Z[j]);
                        myg = 2 * (tid + FPS_T * j) + 1;
                        wx = __uint_as_float(ahi); wy = __uint_as_float(bhi); wz = __uint_as_float(chi);
                        found = true;
                    }
                }
            }
            if (found) atomicMin(s_win, myg);  // first-index tie-break
        }
        __syncthreads();
        int g = *s_win;
        bool owner = (myg == g);
        if (owner) {
            s_last[0] = wx; s_last[1] = wy; s_last[2] = wz;
            g_cx[s + 1] = wx; g_cy[s + 1] = wy; g_cz[s + 1] = wz;
        }
        __syncthreads();
        if (owner) *s_win = 0x7fffffff;  // ordered before next atomicMin by next barriers
    }
}

// ---------------- K2: top-10 nearest per center (1 warp / center) ----------------
__global__ __launch_bounds__(256) void topk_kernel() {
    const int lane = threadIdx.x & 31;
    const int w    = threadIdx.x >> 5;
    const int c    = blockIdx.x * 8 + w;
    const float cx = g_cx[c], cy = g_cy[c], cz = g_cz[c];

    unsigned long long heap[KNB];  // sorted ascending; key = (d2_bits<<32)|idx
#pragma unroll
    for (int q = 0; q < KNB; q++) heap[q] = ~0ULL;

#pragma unroll 4
    for (int i = 0; i < NPTS / 32; i++) {
        int p = lane + 32 * i;
        float dx = __fsub_rn(cx, __ldg(&g_px[p]));   // centers - pos (exact order)
        float dy = __fsub_rn(cy, __ldg(&g_py[p]));
        float dz = __fsub_rn(cz, __ldg(&g_pz[p]));
        float d2 = __fadd_rn(__fadd_rn(__fmul_rn(dx, dx), __fmul_rn(dy, dy)), __fmul_rn(dz, dz));
        unsigned long long key = ((unsigned long long)__float_as_uint(d2) << 32) | (unsigned)p;
        if (key < heap[KNB - 1]) {
            heap[KNB - 1] = key;
#pragma unroll
            for (int q = KNB - 1; q > 0; q--) {
                unsigned long long a = heap[q - 1], b = heap[q];
                heap[q - 1] = (a < b) ? a : b;
                heap[q]     = (a < b) ? b : a;
            }
        }
    }

    // merge 32 sorted lists: 10 rounds of warp-min extraction
#pragma unroll
    for (int r = 0; r < KNB; r++) {
        unsigned long long cur = heap[0];
        unsigned hi = (unsigned)(cur >> 32);
        unsigned mh = __reduce_min_sync(0xffffffffu, hi);
        unsigned lo = (hi == mh) ? (unsigned)cur : 0xffffffffu;
        unsigned ml = __reduce_min_sync(0xffffffffu, lo);
        if (hi == mh && (unsigned)cur == ml) {  // unique popper (idx in key)
#pragma unroll
            for (int q = 0; q < KNB - 1; q++) heap[q] = heap[q + 1];
            heap[KNB - 1] = ~0ULL;
        }
        if (lane == 0)
            g_src[c * KNB + r] = (__uint_as_float(mh) <= R2) ? (int)ml : -1;
    }
}

// ---------------- K3: MLP + masked segment max (1 block / output row) ----------------
__global__ __launch_bounds__(128) void mlp_kernel(const float* __restrict__ W1,
                                                  const float* __restrict__ b1,
                                                  const float* __restrict__ W2,
                                                  const float* __restrict__ b2,
                                                  float* __restrict__ out) {
    const int c = blockIdx.x;
    const int t = threadIdx.x;
    if (c >= NS) {               // rows with no contributions -> 0
        out[c * 128 + t] = 0.0f;
        return;
    }
    __shared__ float s_w2[64 * 128];
    __shared__ float s_hid[64];
    __shared__ int   s_src[KNB];

#pragma unroll
    for (int q = 0; q < 64; q++) s_w2[q * 128 + t] = W2[q * 128 + t];
    if (t < KNB) s_src[t] = g_src[c * KNB + t];

    float w1a = 0.f, w1b = 0.f, w1c = 0.f, bb1 = 0.f;
    if (t < 64) { w1a = W1[t]; w1b = W1[64 + t]; w1c = W1[128 + t]; bb1 = b1[t]; }
    const float bx = g_px[c], by = g_py[c], bz = g_pz[c];  // rel vs pos[:s] row c (per reference)
    const float b2c = b2[t];
    float acc = -3.402823466e38f;
    bool any = false;
    __syncthreads();

    for (int nb = 0; nb < KNB; nb++) {
        int sp = s_src[nb];      // uniform across block
        if (sp >= 0) {
            any = true;
            if (t < 64) {
                float rx = g_px[sp] - bx, ry = g_py[sp] - by, rz = g_pz[sp] - bz;
                float h = bb1 + rx * w1a + ry * w1b + rz * w1c;
                s_hid[t] = h > 0.f ? h : 0.f;
            }
            __syncthreads();
            float a = b2c;
#pragma unroll
            for (int k = 0; k < 64; k++) a = fmaf(s_hid[k], s_w2[k * 128 + t], a);
            acc = fmaxf(acc, a);
            __syncthreads();
        }
    }
    out[c * 128 + t] = any ? acc : 0.0f;
}

// ---------------- launch ----------------
extern "C" void kernel_launch(void* const* d_in, const int* in_sizes, int n_in,
                              void* d_out, int out_size) {
    const float* pos = (const float*)d_in[0];
    // d_in[1] = batch (unused, all zeros)
    const float* W1 = (const float*)d_in[2];
    const float* b1 = (const float*)d_in[3];
    const float* W2 = (const float*)d_in[4];
    const float* b2 = (const float*)d_in[5];
    float* out = (float*)d_out;

    prep_kernel<<<(NPTS + 255) / 256, 256>>>(pos);

    const int fps_smem = (NPTS / 2) * 8 + 32 * 4;  // 64KB min_d + scratch
    cudaFuncSetAttribute(fps_kernel, cudaFuncAttributeMaxDynamicSharedMemorySize, fps_smem);
    fps_kernel<<<1, FPS_T, fps_smem>>>();

    topk_kernel<<<NS / 8, 256>>>();

    mlp_kernel<<<NPTS, 128>>>(W1, b1, W2, b2, out);
}

// round 3
// speedup vs baseline: 1.3316x; 1.3316x over previous
#include <cuda_runtime.h>

#define NPTS 16384
#define NS   8192
#define KNB  10
#define R2   0.0625f
#define FPS_T 512
#define NWARP 16
#define NGRP 256
#define GSZ  64
#define GDIM 8
#define NCELL (GDIM * GDIM * GDIM)

typedef unsigned long long ull;

// ---------------- global scratch (no allocation allowed) ----------------
__device__ __align__(16) float g_px[NPTS];   // original order SoA
__device__ __align__(16) float g_py[NPTS];
__device__ __align__(16) float g_pz[NPTS];
__device__ __align__(16) float g_sx[NPTS];   // spatially sorted SoA
__device__ __align__(16) float g_sy[NPTS];
__device__ __align__(16) float g_sz[NPTS];
__device__ __align__(16) int   g_sidx[NPTS]; // sorted slot -> original index
__device__ int g_cellcnt[NCELL];
__device__ int g_cellcur[NCELL];
__device__ float g_cx[NS], g_cy[NS], g_cz[NS];
__device__ int   g_src[NS * KNB];

// ---------------- packed f32x2 helpers (bit-exact IEEE RN per lane) ----------------
__device__ __forceinline__ ull f2_add(ull a, ull b) {
    ull r; asm("add.rn.f32x2 %0, %1, %2;" : "=l"(r) : "l"(a), "l"(b)); return r;
}
__device__ __forceinline__ ull f2_mul(ull a, ull b) {
    ull r; asm("mul.rn.f32x2 %0, %1, %2;" : "=l"(r) : "l"(a), "l"(b)); return r;
}
__device__ __forceinline__ ull pack2(unsigned lo, unsigned hi) {
    ull r; asm("mov.b64 %0, {%1, %2};" : "=l"(r) : "r"(lo), "r"(hi)); return r;
}
__device__ __forceinline__ void unpack2(unsigned &lo, unsigned &hi, ull v) {
    asm("mov.b64 {%0, %1}, %2;" : "=r"(lo), "=r"(hi) : "l"(v));
}
__device__ __forceinline__ ull umax64(ull a, ull b) { return a > b ? a : b; }
__device__ __forceinline__ ull umin64(ull a, ull b) { return a < b ? a : b; }
__device__ __forceinline__ int cell_of(float x, float y, float z) {
    int cx = min(GDIM - 1, (int)(x * (float)GDIM));
    int cy = min(GDIM - 1, (int)(y * (float)GDIM));
    int cz = min(GDIM - 1, (int)(z * (float)GDIM));
    return (cz * GDIM + cy) * GDIM + cx;
}

// ---------------- K0: AoS -> SoA + zero counters ----------------
__global__ void prep_kernel(const float* __restrict__ pos) {
    int i = blockIdx.x * blockDim.x + threadIdx.x;
    if (i < NCELL) g_cellcnt[i] = 0;
    if (i < NPTS) {
        g_px[i] = pos[3 * i + 0];
        g_py[i] = pos[3 * i + 1];
        g_pz[i] = pos[3 * i + 2];
    }
}
// ---------------- K0b: histogram ----------------
__global__ void hist_kernel() {
    int i = blockIdx.x * blockDim.x + threadIdx.x;
    if (i < NPTS) atomicAdd(&g_cellcnt[cell_of(g_px[i], g_py[i], g_pz[i])], 1);
}
// ---------------- K0c: exclusive scan of cell counts (1 block) ----------------
__global__ __launch_bounds__(NCELL) void scan_kernel() {
    __shared__ int wsum[NCELL / 32];
    int tid = threadIdx.x, lane = tid & 31, wid = tid >> 5;
    int v = g_cellcnt[tid];
    int x = v;
#pragma unroll
    for (int o = 1; o < 32; o <<= 1) {
        int y = __shfl_up_sync(0xffffffffu, x, o);
        if (lane >= o) x += y;
    }
    if (lane == 31) wsum[wid] = x;
    __syncthreads();
    if (wid == 0) {
        int s = (lane < NCELL / 32) ? wsum[lane] : 0;
#pragma unroll
        for (int o = 1; o < 32; o <<= 1) {
            int y = __shfl_up_sync(0xffffffffu, s, o);
            if (lane >= o) s += y;
        }
        if (lane < NCELL / 32) wsum[lane] = s;
    }
    __syncthreads();
    int pre = (wid > 0) ? wsum[wid - 1] : 0;
    g_cellcur[tid] = pre + x - v;
}
// ---------------- K0d: scatter into sorted order (keeps original index) ----------------
__global__ void scatter_kernel() {
    int i = blockIdx.x * blockDim.x + threadIdx.x;
    if (i < NPTS) {
        float x = g_px[i], y = g_py[i], z = g_pz[i];
        int slot = atomicAdd(&g_cellcur[cell_of(x, y, z)], 1);
        g_sx[slot] = x; g_sy[slot] = y; g_sz[slot] = z;
        g_sidx[slot] = i;
    }
}

// ---------------- K1: FPS, box-pruned, tie-exact via (min_d, ~orig_idx) u64 keys ----
// Per-point key = (min_d_bits << 32) | ~orig_idx.  Update = u64 min with the
// candidate (d2_bits<<32)|~idx (same low bits -> pure float-min semantics).
// Global argmax = u64 max over group maxima: max d2, ties -> min ORIGINAL index,
// exactly jnp.argmax. d2 = ((dx*dx+dy*dy)+dz*dz) in RN ops, no FMA (matches XLA).
// A group is skipped iff a conservative lower bound on all its d2 already
// exceeds its max min_d -> update provably a no-op (slack-verified).
__global__ __launch_bounds__(FPS_T, 1) void fps_kernel() {
    extern __shared__ unsigned char smem_raw[];
    ull*   s_key  = (ull*)smem_raw;                  // [NPTS]  128KB
    ull*   s_gkey = s_key + NPTS;                    // [NGRP]
    ull*   s_wk   = s_gkey + NGRP;                   // [NWARP]
    ull*   s_bkey = s_wk + NWARP;                    // [1]
    float* s_bnx  = (float*)(s_bkey + 1);            // box min/max [NGRP] x6
    float* s_bny  = s_bnx + NGRP;
    float* s_bnz  = s_bny + NGRP;
    float* s_bxx  = s_bnz + NGRP;
    float* s_bxy  = s_bxx + NGRP;
    float* s_bxz  = s_bxy + NGRP;
    int*   s_act  = (int*)(s_bxz + NGRP);            // [NGRP]
    int*   s_nact = s_act + NGRP;
    float* s_last = (float*)(s_nact + 1);            // [3]

    const int tid  = threadIdx.x;
    const int lane = tid & 31;
    const int wid  = tid >> 5;

    // init per-point keys: min_d = FLT_MAX, identity = ~orig_idx
#pragma unroll
    for (int j = 0; j < NPTS / FPS_T; j++) {
        int p = tid + FPS_T * j;
        s_key[p] = (0x7f7fffffULL << 32) | (unsigned)(~g_sidx[p]);
    }
    // group bounding boxes (positive coords -> u32 bit order == float order)
    for (int g = wid; g < NGRP; g += NWARP) {
        int base = g * GSZ + 2 * lane;
        float2 x2 = *(const float2*)&g_sx[base];
        float2 y2 = *(const float2*)&g_sy[base];
        float2 z2 = *(const float2*)&g_sz[base];
        unsigned mnx = __reduce_min_sync(0xffffffffu, min(__float_as_uint(x2.x), __float_as_uint(x2.y)));
        unsigned mxx = __reduce_max_sync(0xffffffffu, max(__float_as_uint(x2.x), __float_as_uint(x2.y)));
        unsigned mny = __reduce_min_sync(0xffffffffu, min(__float_as_uint(y2.x), __float_as_uint(y2.y)));
        unsigned mxy = __reduce_max_sync(0xffffffffu, max(__float_as_uint(y2.x), __float_as_uint(y2.y)));
        unsigned mnz = __reduce_min_sync(0xffffffffu, min(__float_as_uint(z2.x), __float_as_uint(z2.y)));
        unsigned mxz = __reduce_max_sync(0xffffffffu, max(__float_as_uint(z2.x), __float_as_uint(z2.y)));
        if (lane == 0) {
            s_bnx[g] = __uint_as_float(mnx); s_bxx[g] = __uint_as_float(mxx);
            s_bny[g] = __uint_as_float(mny); s_bxy[g] = __uint_as_float(mxy);
            s_bnz[g] = __uint_as_float(mnz); s_bxz[g] = __uint_as_float(mxz);
            s_gkey[g] = 0x7f7fffffULL << 32;   // gmax = FLT_MAX -> all active at step 0
        }
    }
    if (tid == 0) {
        float lx = g_px[0], ly = g_py[0], lz = g_pz[0];
        s_last[0] = lx; s_last[1] = ly; s_last[2] = lz;
        *s_nact = 0;
        g_cx[0] = lx; g_cy[0] = ly; g_cz[0] = lz;
    }
    __syncthreads();

    for (int s = 0; s < NS - 1; s++) {
        const float lx = s_last[0], ly = s_last[1], lz = s_last[2];

        // Stage A: box-vs-center pruning, compact active groups
        if (tid < NGRP) {
            float gmax = __uint_as_float((unsigned)(s_gkey[tid] >> 32));
            float bx = fmaxf(fmaxf(s_bnx[tid] - lx, lx - s_bxx[tid]), 0.0f);
            float by = fmaxf(fmaxf(s_bny[tid] - ly, ly - s_bxy[tid]), 0.0f);
            float bz = fmaxf(fmaxf(s_bnz[tid] - lz, lz - s_bxz[tid]), 0.0f);
            float lb = bx * bx + by * by + bz * bz;
            if (lb * 0.99999f - 1e-6f < gmax) {
                int k = atomicAdd(s_nact, 1);
                s_act[k] = tid;
            }
        }
        __syncthreads();
        const int nact = *s_nact;

        // Stage B: update active groups (1 warp : 1 group, 2 pts/lane)
        const unsigned nbx = __float_as_uint(-lx);
        const unsigned nby = __float_as_uint(-ly);
        const unsigned nbz = __float_as_uint(-lz);
        const ull nlx = pack2(nbx, nbx);
        const ull nly = pack2(nby, nby);
        const ull nlz = pack2(nbz, nbz);
        for (int a = wid; a < nact; a += NWARP) {
            const int g = s_act[a];
            const int base = g * GSZ + 2 * lane;
            ull X = __ldg((const ull*)&g_sx[base]);
            ull Y = __ldg((const ull*)&g_sy[base]);
            ull Z = __ldg((const ull*)&g_sz[base]);
            ull dx = f2_add(X, nlx);   // x - lx, exact
            ull dy = f2_add(Y, nly);
            ull dz = f2_add(Z, nlz);
            ull d2 = f2_add(f2_add(f2_mul(dx, dx), f2_mul(dy, dy)), f2_mul(dz, dz));
            unsigned d0u, d1u; unpack2(d0u, d1u, d2);
            ull k0 = s_key[base], k1 = s_key[base + 1];
            k0 = umin64(k0, ((ull)d0u << 32) | (unsigned)k0);
            k1 = umin64(k1, ((ull)d1u << 32) | (unsigned)k1);
            s_key[base] = k0; s_key[base + 1] = k1;
            ull m = umax64(k0, k1);
#pragma unroll
            for (int o = 16; o >= 1; o >>= 1)
                m = umax64(m, __shfl_xor_sync(0xffffffffu, m, o));
            if (lane == 0) s_gkey[g] = m;
        }
        __syncthreads();

        // Stage C: global argmax over group keys (unique total order)
        ull key = (tid < NGRP) ? s_gkey[tid] : 0ULL;
#pragma unroll
        for (int o = 16; o >= 1; o >>= 1)
            key = umax64(key, __shfl_xor_sync(0xffffffffu, key, o));
        if (lane == 0) s_wk[wid] = key;
        __syncthreads();
        if (wid == 0) {
            ull k = (lane < NWARP) ? s_wk[lane] : 0ULL;
#pragma unroll
            for (int o = 8; o >= 1; o >>= 1)
                k = umax64(k, __shfl_xor_sync(0xffffffffu, k, o));
            if (lane == 0) {
                unsigned idx = ~(unsigned)k;     // original index of the winner
                float wx = g_px[idx], wy = g_py[idx], wz = g_pz[idx];
                s_last[0] = wx; s_last[1] = wy; s_last[2] = wz;
                g_cx[s + 1] = wx; g_cy[s + 1] = wy; g_cz[s + 1] = wz;
                *s_nact = 0;
            }
        }
        __syncthreads();
    }
}

// ---------------- K2: top-10 nearest per center (1 warp / center) ----------------
__global__ __launch_bounds__(256) void topk_kernel() {
    const int lane = threadIdx.x & 31;
    const int w    = threadIdx.x >> 5;
    const int c    = blockIdx.x * 8 + w;
    const float cx = g_cx[c], cy = g_cy[c], cz = g_cz[c];

    ull heap[KNB];  // sorted ascending; key = (d2_bits<<32)|idx
#pragma unroll
    for (int q = 0; q < KNB; q++) heap[q] = ~0ULL;

#pragma unroll 4
    for (int i = 0; i < NPTS / 32; i++) {
        int p = lane + 32 * i;
        float dx = __fsub_rn(cx, __ldg(&g_px[p]));
        float dy = __fsub_rn(cy, __ldg(&g_py[p]));
        float dz = __fsub_rn(cz, __ldg(&g_pz[p]));
        float d2 = __fadd_rn(__fadd_rn(__fmul_rn(dx, dx), __fmul_rn(dy, dy)), __fmul_rn(dz, dz));
        ull key = ((ull)__float_as_uint(d2) << 32) | (unsigned)p;
        if (key < heap[KNB - 1]) {
            heap[KNB - 1] = key;
#pragma unroll
            for (int q = KNB - 1; q > 0; q--) {
                ull a = heap[q - 1], b = heap[q];
                heap[q - 1] = (a < b) ? a : b;
                heap[q]     = (a < b) ? b : a;
            }
        }
    }
#pragma unroll
    for (int r = 0; r < KNB; r++) {
        ull cur = heap[0];
        unsigned hi = (unsigned)(cur >> 32);
        unsigned mh = __reduce_min_sync(0xffffffffu, hi);
        unsigned lo = (hi == mh) ? (unsigned)cur : 0xffffffffu;
        unsigned ml = __reduce_min_sync(0xffffffffu, lo);
        if (hi == mh && (unsigned)cur == ml) {
#pragma unroll
            for (int q = 0; q < KNB - 1; q++) heap[q] = heap[q + 1];
            heap[KNB - 1] = ~0ULL;
        }
        if (lane == 0)
            g_src[c * KNB + r] = (__uint_as_float(mh) <= R2) ? (int)ml : -1;
    }
}

// ---------------- K3: MLP + masked segment max (1 block / output row) ----------------
__global__ __launch_bounds__(128) void mlp_kernel(const float* __restrict__ W1,
                                                  const float* __restrict__ b1,
                                                  const float* __restrict__ W2,
                                                  const float* __restrict__ b2,
                                                  float* __restrict__ out) {
    const int c = blockIdx.x;
    const int t = threadIdx.x;
    if (c >= NS) {
        out[c * 128 + t] = 0.0f;
        return;
    }
    __shared__ float s_w2[64 * 128];
    __shared__ float s_hid[64];
    __shared__ int   s_src[KNB];

#pragma unroll
    for (int q = 0; q < 64; q++) s_w2[q * 128 + t] = W2[q * 128 + t];
    if (t < KNB) s_src[t] = g_src[c * KNB + t];

    float w1a = 0.f, w1b = 0.f, w1c = 0.f, bb1 = 0.f;
    if (t < 64) { w1a = W1[t]; w1b = W1[64 + t]; w1c = W1[128 + t]; bb1 = b1[t]; }
    const float bx = g_px[c], by = g_py[c], bz = g_pz[c];
    const float b2c = b2[t];
    float acc = -3.402823466e38f;
    bool any = false;
    __syncthreads();

    for (int nb = 0; nb < KNB; nb++) {
        int sp = s_src[nb];
        if (sp >= 0) {
            any = true;
            if (t < 64) {
                float rx = g_px[sp] - bx, ry = g_py[sp] - by, rz = g_pz[sp] - bz;
                float h = bb1 + rx * w1a + ry * w1b + rz * w1c;
                s_hid[t] = h > 0.f ? h : 0.f;
            }
            __syncthreads();
            float a = b2c;
#pragma unroll
            for (int k = 0; k < 64; k++) a = fmaf(s_hid[k], s_w2[k * 128 + t], a);
            acc = fmaxf(acc, a);
            __syncthreads();
        }
    }
    out[c * 128 + t] = any ? acc : 0.0f;
}

// ---------------- launch ----------------
extern "C" void kernel_launch(void* const* d_in, const int* in_sizes, int n_in,
                              void* d_out, int out_size) {
    const float* pos = (const float*)d_in[0];
    const float* W1 = (const float*)d_in[2];
    const float* b1 = (const float*)d_in[3];
    const float* W2 = (const float*)d_in[4];
    const float* b2 = (const float*)d_in[5];
    float* out = (float*)d_out;

    prep_kernel<<<(NPTS + 255) / 256, 256>>>(pos);
    hist_kernel<<<(NPTS + 255) / 256, 256>>>();
    scan_kernel<<<1, NCELL>>>();
    scatter_kernel<<<(NPTS + 255) / 256, 256>>>();

    const int fps_smem = NPTS * 8                      // s_key
                       + NGRP * 8 + NWARP * 8 + 8      // s_gkey, s_wk, s_bkey
                       + NGRP * 4 * 6                  // boxes
                       + NGRP * 4 + 16;                // s_act, s_nact, s_last
    cudaFuncSetAttribute(fps_kernel, cudaFuncAttributeMaxDynamicSharedMemorySize, fps_smem);
    fps_kernel<<<1, FPS_T, fps_smem>>>();

    topk_kernel<<<NS / 8, 256>>>();

    mlp_kernel<<<NPTS, 128>>>(W1, b1, W2, b2, out);
}